// round 16
// baseline (speedup 1.0000x reference)
#include <cuda_runtime.h>
#include <cuda_bf16.h>
#include <cstdint>

// CASSI forward A^T(A(x)); coded aperture is band-broadcast (phi[l]==phi2d):
//   y2[b,m,j]    = sum_{l : 0<=j-2l<N} x[b,l,m,j-2l]*phi2d[m,j-2l]
//   out[b,l,m,n] = phi2d[m,n] * y2[b,m,n+2l]
// One CTA per (b,m) row. L=28, M=N=256, STRIDE=2, n_out=310.
//
// R16 = R9 champion with phase 1 replaced by TMA bulk-async copies:
//   - 28 x cp.async.bulk (1KB each, lanes 0..27 of warp 0) DMA raw x rows
//     global->SMEM through the TMA engine: zero LDG/STS L1 wavefronts.
//   - phi multiply moves into phase 2 (xs * phiS, staged 1KB phi row).
//   - phase 3 identical to champion (register phi + dual y2/y2s LDS.128).

#define LBANDS 28
#define NCOLS  256
#define NC4    (NCOLS / 4)                        // 64 float4 per row
#define NOUT   (NCOLS + 2 * (LBANDS - 1))         // 310
#define THREADS 256
#define MNFIX  (NCOLS * NCOLS)
#define BAND4  (MNFIX / 4)                        // float4 stride between bands
#define ROWBYTES (NCOLS * 4)                      // 1024 B per band row
#define TILEBYTES (LBANDS * ROWBYTES)             // 28672 B

__global__ __launch_bounds__(THREADS, 6)
void cassi_kernel(const float* __restrict__ x,
                  const float4* __restrict__ phi4,
                  float4* __restrict__ out4,
                  int LMN4 /* L*M*N/4 */)
{
    __shared__ __align__(16) float xs[LBANDS * NCOLS];  // raw x tile, 28 KB
    __shared__ __align__(16) float phiS[NCOLS];         // phi2d row, 1 KB
    __shared__ float y2 [320];
    __shared__ float y2s[320];                          // y2s[j] == y2[j+2]
    __shared__ __align__(8) uint64_t mbar;

    const int m   = blockIdx.x;
    const int b   = blockIdx.y;
    const int tid = threadIdx.x;

    const int lsub = tid >> 6;        // 0..3, uniform per warp-pair
    const int c    = tid & 63;        // float4 column 0..63

    const int xrow4 = b * LMN4 + m * NC4;        // x/out row base (float4 units)

    const uint32_t mbar_a = (uint32_t)__cvta_generic_to_shared(&mbar);
    const uint32_t xs_a   = (uint32_t)__cvta_generic_to_shared(xs);

    // ---- mbarrier init ----
    if (tid == 0) {
        asm volatile("mbarrier.init.shared.b64 [%0], %1;"
                     :: "r"(mbar_a), "r"(1) : "memory");
    }
    __syncthreads();

    // ---- phase 1: 28 bulk-async copies, lanes 0..27 of warp 0 ----
    if (tid == 0) {
        asm volatile("mbarrier.arrive.expect_tx.shared.b64 _, [%0], %1;"
                     :: "r"(mbar_a), "r"((uint32_t)TILEBYTES) : "memory");
    }
    __syncwarp();
    if (tid < LBANDS) {
        const uint64_t gsrc = (uint64_t)__cvta_generic_to_global(
            x + (size_t)(xrow4 + tid * BAND4) * 4);
        asm volatile(
            "cp.async.bulk.shared::cta.global.mbarrier::complete_tx::bytes "
            "[%0], [%1], %2, [%3];"
            :: "r"(xs_a + tid * ROWBYTES), "l"(gsrc),
               "r"((uint32_t)ROWBYTES), "r"(mbar_a)
            : "memory");
    }

    // ---- overlap: stage phi row + register copy (band-independent) ----
    const float4 pv = phi4[m * NC4 + c];
    if (lsub == 0)                                // tid 0..63: one STS.128 each
        reinterpret_cast<float4*>(phiS)[c] = pv;
    __syncthreads();                              // phiS visible

    // wait for TMA tile
    {
        uint32_t done;
        asm volatile(
            "{\n\t.reg .pred p;\n\t"
            "mbarrier.try_wait.parity.shared.b64 p, [%1], %2;\n\t"
            "selp.b32 %0, 1, 0, p;\n\t}"
            : "=r"(done) : "r"(mbar_a), "r"(0u) : "memory");
        while (!done) {
            asm volatile(
                "{\n\t.reg .pred p;\n\t"
                "mbarrier.try_wait.parity.shared.b64 p, [%1], %2;\n\t"
                "selp.b32 %0, 1, 0, p;\n\t}"
                : "=r"(done) : "r"(mbar_a), "r"(0u) : "memory");
        }
    }

    // ---- phase 2: y2[j],y2[j+1] (j even) = sum_l xs[l][j-2l]*phiS[j-2l] ----
    {
        const int j = tid << 1;                   // 0,2,...,510
        if (j < NOUT) {
            const int lmin = (j >= NCOLS) ? ((j - (NCOLS - 2)) >> 1) : 0;
            const int jh   = j >> 1;
            const int lmax = jh < (LBANDS - 1) ? jh : (LBANDS - 1);
            float sx = 0.0f, sy = 0.0f;
            const float* xb = xs + j;
            const float* fb = phiS + j;
            for (int l = lmin; l <= lmax; ++l) {
                const float2 xv =
                    *reinterpret_cast<const float2*>(xb + l * (NCOLS - 2));
                const float2 fv =
                    *reinterpret_cast<const float2*>(fb - 2 * l);
                sx += xv.x * fv.x;
                sy += xv.y * fv.y;
            }
            y2[j]     = sx;
            y2[j + 1] = sy;
            if (j >= 2) {
                y2s[j - 2] = sx;
                y2s[j - 1] = sy;
            }
        }
    }
    __syncthreads();

    // ---- phase 3: out = phi * y2[n+2l]; phi from register, y2 via LDS.128 ----
    {
        const float* ybase = (lsub & 1) ? y2s : y2;
        int yo4 = ((c << 2) + 2 * lsub - ((lsub & 1) << 1)) >> 2;
        int oo  = xrow4 + lsub * BAND4 + c;
#pragma unroll
        for (int k = 0; k < LBANDS / 4; ++k) {
            const float4 yv = reinterpret_cast<const float4*>(ybase)[yo4];
            float4 ov;
            ov.x = pv.x * yv.x; ov.y = pv.y * yv.y;
            ov.z = pv.z * yv.z; ov.w = pv.w * yv.w;
            out4[oo] = ov;
            oo += 4 * BAND4;
            yo4 += 2;                      // 4 bands * stride 2 = 8 floats
        }
    }
}

extern "C" void kernel_launch(void* const* d_in, const int* in_sizes, int n_in,
                              void* d_out, int out_size)
{
    const float*  x    = (const float*)d_in[0];    // [B, L, M, N]
    const float4* phi4 = (const float4*)d_in[1];   // [L, M, N] (band-broadcast)
    float4* out4 = (float4*)d_out;

    const int LMN  = in_sizes[1];        // L*M*N
    const int B    = in_sizes[0] / LMN;  // batch
    const int LMN4 = LMN / 4;

    dim3 grid(NCOLS /* M */, B);
    cassi_kernel<<<grid, THREADS>>>(x, phi4, out4, LMN4);
}

// round 17
// speedup vs baseline: 1.0223x; 1.0223x over previous
#include <cuda_runtime.h>
#include <cuda_bf16.h>
#include <cstdint>

// CASSI forward A^T(A(x)); coded aperture is band-broadcast (phi[l]==phi2d):
//   y2[b,m,j]    = sum_{l : 0<=j-2l<N} x[b,l,m,j-2l]*phi2d[m,j-2l]
//   out[b,l,m,n] = phi2d[m,n] * y2[b,m,n+2l]
// One CTA per (b,m) row. L=28, M=N=256, STRIDE=2, n_out=310.
//
// R17 = R16 TMA load, split into TWO 14-band half-tiles with separate
// mbarriers: phase 2 starts when half 0 lands and accumulates half 1 in
// registers after the second wait — overlaps tile-arrival tail with compute.
// SMEM 31.5KB keeps the 6 CTAs/SM sweet spot. Phase 3 = champion (R9).

#define LBANDS 28
#define HBANDS 14
#define NCOLS  256
#define NC4    (NCOLS / 4)
#define NOUT   (NCOLS + 2 * (LBANDS - 1))   // 310
#define THREADS 256
#define MNFIX  (NCOLS * NCOLS)
#define BAND4  (MNFIX / 4)                  // float4 stride between bands
#define ROWBYTES (NCOLS * 4)                // 1024 B per band row
#define HALFBYTES (HBANDS * ROWBYTES)       // 14336 B per half tile

__global__ __launch_bounds__(THREADS, 6)
void cassi_kernel(const float* __restrict__ x,
                  const float4* __restrict__ phi4,
                  float4* __restrict__ out4,
                  int LMN4 /* L*M*N/4 */)
{
    __shared__ __align__(16) float xs0[HBANDS * NCOLS];  // bands 0..13, 14 KB
    __shared__ __align__(16) float xs1[HBANDS * NCOLS];  // bands 14..27, 14 KB
    __shared__ __align__(16) float phiS[NCOLS];          // phi2d row, 1 KB
    __shared__ float y2 [320];
    __shared__ float y2s[320];                           // y2s[j] == y2[j+2]
    __shared__ __align__(8) uint64_t mbar[2];

    const int m   = blockIdx.x;
    const int b   = blockIdx.y;
    const int tid = threadIdx.x;

    const int lsub = tid >> 6;        // 0..3, uniform per warp-pair
    const int c    = tid & 63;        // float4 column 0..63

    const int xrow4 = b * LMN4 + m * NC4;    // x/out row base (float4 units)

    const uint32_t mb0 = (uint32_t)__cvta_generic_to_shared(&mbar[0]);
    const uint32_t mb1 = (uint32_t)__cvta_generic_to_shared(&mbar[1]);
    const uint32_t xs0a = (uint32_t)__cvta_generic_to_shared(xs0);
    const uint32_t xs1a = (uint32_t)__cvta_generic_to_shared(xs1);

    // ---- mbarrier init ----
    if (tid == 0) {
        asm volatile("mbarrier.init.shared.b64 [%0], %1;" :: "r"(mb0), "r"(1) : "memory");
        asm volatile("mbarrier.init.shared.b64 [%0], %1;" :: "r"(mb1), "r"(1) : "memory");
    }
    __syncthreads();

    // ---- issue all 28 bulk copies (warp 0), halves on separate barriers ----
    if (tid == 0) {
        asm volatile("mbarrier.arrive.expect_tx.shared.b64 _, [%0], %1;"
                     :: "r"(mb0), "r"((uint32_t)HALFBYTES) : "memory");
        asm volatile("mbarrier.arrive.expect_tx.shared.b64 _, [%0], %1;"
                     :: "r"(mb1), "r"((uint32_t)HALFBYTES) : "memory");
    }
    __syncwarp();
    if (tid < LBANDS) {
        const int      half = (tid >= HBANDS);
        const uint32_t dst  = half ? xs1a + (tid - HBANDS) * ROWBYTES
                                   : xs0a + tid * ROWBYTES;
        const uint32_t mb   = half ? mb1 : mb0;
        const uint64_t gsrc = (uint64_t)__cvta_generic_to_global(
            x + (size_t)(xrow4 + tid * BAND4) * 4);
        asm volatile(
            "cp.async.bulk.shared::cta.global.mbarrier::complete_tx::bytes "
            "[%0], [%1], %2, [%3];"
            :: "r"(dst), "l"(gsrc), "r"((uint32_t)ROWBYTES), "r"(mb)
            : "memory");
    }

    // ---- overlap: stage phi row + register copy (band-independent) ----
    const float4 pv = phi4[m * NC4 + c];
    if (lsub == 0)
        reinterpret_cast<float4*>(phiS)[c] = pv;
    __syncthreads();                              // phiS visible

    // ---- phase 2, per thread j-pair; accumulate both halves in registers ----
    const int j = tid << 1;                       // 0,2,...,510
    float sx = 0.0f, sy = 0.0f;
    int lmin = 0, lmax = -1;
    if (j < NOUT) {
        lmin = (j >= NCOLS) ? ((j - (NCOLS - 2)) >> 1) : 0;
        const int jh = j >> 1;
        lmax = jh < (LBANDS - 1) ? jh : (LBANDS - 1);
    }

    // wait half 0 (bands 0..13)
    {
        uint32_t done = 0;
        do {
            asm volatile(
                "{\n\t.reg .pred p;\n\t"
                "mbarrier.try_wait.parity.shared.b64 p, [%1], %2;\n\t"
                "selp.b32 %0, 1, 0, p;\n\t}"
                : "=r"(done) : "r"(mb0), "r"(0u) : "memory");
        } while (!done);
    }
    {
        const int l1 = lmax < (HBANDS - 1) ? lmax : (HBANDS - 1);
        const float* xb = xs0 + j;
        const float* fb = phiS + j;
        for (int l = lmin; l <= l1; ++l) {
            const float2 xv = *reinterpret_cast<const float2*>(xb + l * (NCOLS - 2));
            const float2 fv = *reinterpret_cast<const float2*>(fb - 2 * l);
            sx += xv.x * fv.x;
            sy += xv.y * fv.y;
        }
    }

    // wait half 1 (bands 14..27)
    {
        uint32_t done = 0;
        do {
            asm volatile(
                "{\n\t.reg .pred p;\n\t"
                "mbarrier.try_wait.parity.shared.b64 p, [%1], %2;\n\t"
                "selp.b32 %0, 1, 0, p;\n\t}"
                : "=r"(done) : "r"(mb1), "r"(0u) : "memory");
        } while (!done);
    }
    {
        const int l0 = lmin > HBANDS ? lmin : HBANDS;
        // xs1 index (l-14)*256 + (j-2l) = (xs1 + j - 14*256) + l*(256-2)
        const float* xb = xs1 + j - HBANDS * NCOLS;
        const float* fb = phiS + j;
        for (int l = l0; l <= lmax; ++l) {
            const float2 xv = *reinterpret_cast<const float2*>(xb + l * (NCOLS - 2));
            const float2 fv = *reinterpret_cast<const float2*>(fb - 2 * l);
            sx += xv.x * fv.x;
            sy += xv.y * fv.y;
        }
    }

    if (j < NOUT) {
        y2[j]     = sx;
        y2[j + 1] = sy;
        if (j >= 2) {
            y2s[j - 2] = sx;
            y2s[j - 1] = sy;
        }
    }
    __syncthreads();

    // ---- phase 3: out = phi * y2[n+2l]; phi from register, y2 via LDS.128 ----
    {
        const float* ybase = (lsub & 1) ? y2s : y2;
        int yo4 = ((c << 2) + 2 * lsub - ((lsub & 1) << 1)) >> 2;
        int oo  = xrow4 + lsub * BAND4 + c;
#pragma unroll
        for (int k = 0; k < LBANDS / 4; ++k) {
            const float4 yv = reinterpret_cast<const float4*>(ybase)[yo4];
            float4 ov;
            ov.x = pv.x * yv.x; ov.y = pv.y * yv.y;
            ov.z = pv.z * yv.z; ov.w = pv.w * yv.w;
            out4[oo] = ov;
            oo += 4 * BAND4;
            yo4 += 2;
        }
    }
}

extern "C" void kernel_launch(void* const* d_in, const int* in_sizes, int n_in,
                              void* d_out, int out_size)
{
    const float*  x    = (const float*)d_in[0];    // [B, L, M, N]
    const float4* phi4 = (const float4*)d_in[1];   // [L, M, N] (band-broadcast)
    float4* out4 = (float4*)d_out;

    const int LMN  = in_sizes[1];        // L*M*N
    const int B    = in_sizes[0] / LMN;  // batch
    const int LMN4 = LMN / 4;

    dim3 grid(NCOLS /* M */, B);
    cassi_kernel<<<grid, THREADS>>>(x, phi4, out4, LMN4);
}